// round 6
// baseline (speedup 1.0000x reference)
#include <cuda_runtime.h>

#define DIMN 32
#define TPB 256
#define BLOCKS_PER_SM 4

__device__ unsigned long long g_wp[DIMN];

__device__ __forceinline__ unsigned long long pack2(float lo, float hi) {
    unsigned long long r;
    asm("mov.b64 %0, {%1, %2};" : "=l"(r) : "f"(lo), "f"(hi));
    return r;
}
__device__ __forceinline__ void unpack2(unsigned long long v, float& lo, float& hi) {
    asm("mov.b64 {%0, %1}, %2;" : "=f"(lo), "=f"(hi) : "l"(v));
}
__device__ __forceinline__ unsigned long long fma2(unsigned long long a,
                                                   unsigned long long b,
                                                   unsigned long long c) {
    unsigned long long d;
    asm("fma.rn.f32x2 %0, %1, %2, %3;" : "=l"(d) : "l"(a), "l"(b), "l"(c));
    return d;
}

// Pre-pack (w_k, w_k) pairs once.
__global__ void pack_w_kernel(const float* __restrict__ w) {
    int k = threadIdx.x;
    if (k < DIMN) {
        float wk = w[k];
        g_wp[k] = pack2(wk, wk);
    }
}

__global__ __launch_bounds__(TPB) void poly_persistent_kernel(
    const float* __restrict__ x,
    float* __restrict__ out,
    int n_vec4)
{
    __shared__ unsigned long long s_wp[DIMN];
    if (threadIdx.x < DIMN) s_wp[threadIdx.x] = g_wp[threadIdx.x];
    __syncthreads();

    const float4* __restrict__ x4 = reinterpret_cast<const float4*>(x);
    float4* __restrict__ o4 = reinterpret_cast<float4*>(out);

    const int stride = gridDim.x * TPB;              // float4s per grid step
    int i = blockIdx.x * TPB + threadIdx.x;

    // Prime the pipeline: load the first tile.
    float4 cur = (i < n_vec4) ? __ldg(&x4[i]) : make_float4(0.f, 0.f, 0.f, 0.f);

    while (i < n_vec4) {
        // Prefetch next tile BEFORE the compute burst (independent -> hoisted LDG).
        int inext = i + stride;
        float4 nxt = (inext < n_vec4) ? __ldg(&x4[inext])
                                      : make_float4(0.f, 0.f, 0.f, 0.f);

        // Two independent packed Horner chains over the current tile.
        unsigned long long p0 = pack2(cur.x, cur.y);
        unsigned long long p1 = pack2(cur.z, cur.w);
        unsigned long long a0 = s_wp[DIMN - 1];
        unsigned long long a1 = a0;

#pragma unroll
        for (int k = DIMN - 2; k >= 0; --k) {
            unsigned long long wk = s_wp[k];
            a0 = fma2(a0, p0, wk);
            a1 = fma2(a1, p1, wk);
        }

        float4 ov;
        unpack2(a0, ov.x, ov.y);
        unpack2(a1, ov.z, ov.w);
        o4[i] = ov;

        cur = nxt;
        i = inext;
    }
}

extern "C" void kernel_launch(void* const* d_in, const int* in_sizes, int n_in,
                              void* d_out, int out_size) {
    const float* x = (const float*)d_in[0];
    const float* w = (const float*)d_in[1];
    float* out = (float*)d_out;

    int n = in_sizes[0];            // 4194304
    int n_vec4 = n / 4;             // 1048576 float4s

    int sms = 148;
    cudaDeviceGetAttribute(&sms, cudaDevAttrMultiProcessorCount, 0);
    int blocks = sms * BLOCKS_PER_SM;        // single exact wave
    int max_blocks = (n_vec4 + TPB - 1) / TPB;
    if (blocks > max_blocks) blocks = max_blocks;

    pack_w_kernel<<<1, DIMN>>>(w);
    poly_persistent_kernel<<<blocks, TPB>>>(x, out, n_vec4);
}

// round 7
// speedup vs baseline: 1.1693x; 1.1693x over previous
#include <cuda_runtime.h>

#define DIMN 32
#define TPB 256

__device__ unsigned long long g_wp[DIMN];

__device__ __forceinline__ unsigned long long pack2(float lo, float hi) {
    unsigned long long r;
    asm("mov.b64 %0, {%1, %2};" : "=l"(r) : "f"(lo), "f"(hi));
    return r;
}
__device__ __forceinline__ void unpack2(unsigned long long v, float& lo, float& hi) {
    asm("mov.b64 {%0, %1}, %2;" : "=f"(lo), "=f"(hi) : "l"(v));
}
__device__ __forceinline__ unsigned long long fma2(unsigned long long a,
                                                   unsigned long long b,
                                                   unsigned long long c) {
    unsigned long long d;
    asm("fma.rn.f32x2 %0, %1, %2, %3;" : "=l"(d) : "l"(a), "l"(b), "l"(c));
    return d;
}

// Pre-pack (w_k, w_k) pairs once.
__global__ void pack_w_kernel(const float* __restrict__ w) {
    int k = threadIdx.x;
    if (k < DIMN) {
        float wk = w[k];
        g_wp[k] = pack2(wk, wk);
    }
}

// Evaluate one 4-float4 tile (8 packed Horner chains) and store it.
__device__ __forceinline__ void eval_store_tile(
    const float4 xv[4],
    const unsigned long long* s_wp,
    float4* __restrict__ o4,
    int base4, int n_vec4)
{
    unsigned long long p[8];
#pragma unroll
    for (int j = 0; j < 4; ++j) {
        p[2 * j + 0] = pack2(xv[j].x, xv[j].y);
        p[2 * j + 1] = pack2(xv[j].z, xv[j].w);
    }

    unsigned long long a[8];
    unsigned long long w31 = s_wp[DIMN - 1];
#pragma unroll
    for (int c = 0; c < 8; ++c) a[c] = w31;

#pragma unroll
    for (int k = DIMN - 2; k >= 0; --k) {
        unsigned long long wk = s_wp[k];
#pragma unroll
        for (int c = 0; c < 8; ++c) a[c] = fma2(a[c], p[c], wk);
    }

#pragma unroll
    for (int j = 0; j < 4; ++j) {
        int idx = base4 + j * TPB;
        if (idx < n_vec4) {
            float4 ov;
            unpack2(a[2 * j + 0], ov.x, ov.y);
            unpack2(a[2 * j + 1], ov.z, ov.w);
            o4[idx] = ov;
        }
    }
}

__global__ __launch_bounds__(TPB) void poly_pipelined_kernel(
    const float* __restrict__ x,
    float* __restrict__ out,
    int n_vec4)
{
    __shared__ unsigned long long s_wp[DIMN];
    if (threadIdx.x < DIMN) s_wp[threadIdx.x] = g_wp[threadIdx.x];
    __syncthreads();

    const float4* __restrict__ x4 = reinterpret_cast<const float4*>(x);
    float4* __restrict__ o4 = reinterpret_cast<float4*>(out);

    // Block owns 2 tiles of TPB*4 consecutive float4s each (2048 f4 total).
    int baseA = blockIdx.x * (TPB * 8) + threadIdx.x;
    int baseB = baseA + TPB * 4;

    // ---- issue ALL loads for both tiles up front (MLP=8, one fill) ----
    float4 xa[4], xb[4];
#pragma unroll
    for (int j = 0; j < 4; ++j) {
        int ia = baseA + j * TPB;
        xa[j] = (ia < n_vec4) ? __ldg(&x4[ia]) : make_float4(0.f, 0.f, 0.f, 0.f);
    }
#pragma unroll
    for (int j = 0; j < 4; ++j) {
        int ib = baseB + j * TPB;
        xb[j] = (ib < n_vec4) ? __ldg(&x4[ib]) : make_float4(0.f, 0.f, 0.f, 0.f);
    }

    // ---- tile A compute+store (tile B data arrives in the shadow) ----
    eval_store_tile(xa, s_wp, o4, baseA, n_vec4);
    // ---- tile B compute+store ----
    eval_store_tile(xb, s_wp, o4, baseB, n_vec4);
}

extern "C" void kernel_launch(void* const* d_in, const int* in_sizes, int n_in,
                              void* d_out, int out_size) {
    const float* x = (const float*)d_in[0];
    const float* w = (const float*)d_in[1];
    float* out = (float*)d_out;

    int n = in_sizes[0];            // 4194304
    int n_vec4 = n / 4;             // 1048576 float4s
    int blocks = (n_vec4 + TPB * 8 - 1) / (TPB * 8);  // 512

    pack_w_kernel<<<1, DIMN>>>(w);
    poly_pipelined_kernel<<<blocks, TPB>>>(x, out, n_vec4);
}